// round 3
// baseline (speedup 1.0000x reference)
#include <cuda_runtime.h>

// Shapes: re, gt are (B=32, C=10, H=192, W=320) float32, contiguous.
#define NB     32
#define NC     10
#define HW4    15360                  // (192*320)/4 float4 groups per channel
#define N4     (NB*HW4)               // 491520 groups total
#define GRID   960
#define BLK    256
#define STRIDE (GRID*BLK)             // 245760 -> exactly 2 groups per thread
#define NACC   11

// [0]=nv [1]=num_pos [2]=pos_term [3]=neg_term [4]=S_pos
// [5]=S_len1 [6]=S_len2 [7]=S_trig1 [8]=S_trig2 [9]=S_const [10]=S_h
// Per-block partials, overwritten every launch (no zeroing / atomics needed).
__device__ float g_part[NACC][GRID];

__device__ __forceinline__ float sl1(float d) {
    float ad = fabsf(d);
    return ad < 1.0f ? 0.5f * d * d : ad - 0.5f;
}

__device__ __forceinline__ float c4(const float4& v, int j) {
    return j == 0 ? v.x : (j == 1 ? v.y : (j == 2 ? v.z : v.w));
}

__global__ void __launch_bounds__(BLK)
loss_kernel(const float* __restrict__ re, const float* __restrict__ gt) {
    float acc[NACC];
#pragma unroll
    for (int k = 0; k < NACC; k++) acc[k] = 0.0f;

    const float4* __restrict__ re4 = (const float4*)re;
    const float4* __restrict__ gt4 = (const float4*)gt;

    const int t = blockIdx.x * BLK + threadIdx.x;

    // Precompute both groups' base offsets and issue all 4 channel-0 loads
    // up front (one latency window, MLP=4).
    int base[2];
    float4 G0[2], R0[2];
#pragma unroll
    for (int it = 0; it < 2; it++) {
        int i   = t + it * STRIDE;
        int b   = i / HW4;
        int hw4 = i - b * HW4;
        base[it] = b * (NC * HW4) + hw4;
        G0[it] = gt4[base[it]];
        R0[it] = re4[base[it]];
    }

#pragma unroll
    for (int it = 0; it < 2; it++) {
        const int bs = base[it];
        const float4 G = G0[it];
        const float4 R = R0[it];

        bool mv[4];
        bool any = false;
#pragma unroll
        for (int j = 0; j < 4; j++) {
            float g = c4(G, j);
            float r = c4(R, j);
            bool m = (g == 1.0f);
            mv[j] = m;
            any |= m;
            if (m) acc[0] += 1.0f;
            if (g >= 0.0f) {
                float safe = fminf(fmaxf(r, 1e-6f), 1.0f - 1e-6f);
                if (g >= 0.1f) {                       // FOCAL_THR
                    acc[1] += 1.0f;
                    float d = g - r;
                    acc[2] -= d * d * __logf(safe + 6e-8f);
                } else {
                    float om  = 1.0f - g;
                    float om2 = om * om;
                    acc[3] -= r * r * __logf(1.0f + 6e-8f - safe) * om2 * om2;
                }
            }
        }

        if (any) {
            // Issue ALL 18 channel loads in one window (MLP=18); compute after.
            float4 R1 = re4[bs + 1*HW4], G1 = gt4[bs + 1*HW4];
            float4 R2 = re4[bs + 2*HW4], G2 = gt4[bs + 2*HW4];
            float4 R3 = re4[bs + 3*HW4], G3 = gt4[bs + 3*HW4];
            float4 R4 = re4[bs + 4*HW4], G4 = gt4[bs + 4*HW4];
            float4 R5 = re4[bs + 5*HW4], G5 = gt4[bs + 5*HW4];
            float4 R6 = re4[bs + 6*HW4], G6 = gt4[bs + 6*HW4];
            float4 R7 = re4[bs + 7*HW4], G7 = gt4[bs + 7*HW4];
            float4 R8 = re4[bs + 8*HW4], G8 = gt4[bs + 8*HW4];
            float4 R9 = re4[bs + 9*HW4], G9 = gt4[bs + 9*HW4];

#pragma unroll
            for (int j = 0; j < 4; j++) {
                if (!mv[j]) continue;
                acc[4] += sl1(c4(R1,j) - c4(G1,j)) + sl1(c4(R2,j) - c4(G2,j));

                float r3 = c4(R3,j), g3 = c4(G3,j);
                float r6 = c4(R6,j), g6 = c4(G6,j);
                acc[5] += sl1(r3 - g3) + sl1(r6 - g6);
                acc[6] += sl1(r3 - g6) + sl1(r6 - g3);

                float r4 = c4(R4,j), g4 = c4(G4,j);
                float r5 = c4(R5,j), g5 = c4(G5,j);
                float r7 = c4(R7,j), g7 = c4(G7,j);
                float r8 = c4(R8,j), g8 = c4(G8,j);
                float d44 = r4 - g4, d77 = r7 - g7;
                float d55 = r5 - g5, d88 = r8 - g8;
                acc[7] += d44*d44 + d77*d77 + d55*d55 + d88*d88;
                float d47 = r4 - g7, d74 = r7 - g4;
                float d58 = r5 - g8, d85 = r8 - g5;
                acc[8] += d47*d47 + d74*d74 + d58*d58 + d85*d85;
                float c1 = 1.0f - r5*r5 - r4*r4;
                float c2 = 1.0f - r8*r8 - r7*r7;
                acc[9] += c1*c1 + c2*c2;

                acc[10] += sl1(c4(R9,j) - c4(G9,j));
            }
        }
    }

    // Block reduction: warp shuffle -> shared -> per-block partial slot.
    __shared__ float sh[BLK/32][NACC];
    int lane = threadIdx.x & 31;
    int warp = threadIdx.x >> 5;
#pragma unroll
    for (int k = 0; k < NACC; k++) {
        float v = acc[k];
#pragma unroll
        for (int o = 16; o > 0; o >>= 1)
            v += __shfl_down_sync(0xffffffffu, v, o);
        if (lane == 0) sh[warp][k] = v;
    }
    __syncthreads();
    if (threadIdx.x < NACC) {
        float v = 0.0f;
#pragma unroll
        for (int w = 0; w < BLK/32; w++) v += sh[w][threadIdx.x];
        g_part[threadIdx.x][blockIdx.x] = v;   // overwrite -> no zeroing needed
    }
}

// One block, 11 warps: warp k reduces accumulator k over all 960 block partials.
__global__ void __launch_bounds__(NACC*32)
finalize_kernel(float* __restrict__ out) {
    __shared__ float tot[NACC];
    int warp = threadIdx.x >> 5;
    int lane = threadIdx.x & 31;

    float v = 0.0f;
    for (int j = lane; j < GRID; j += 32) v += g_part[warp][j];
#pragma unroll
    for (int o = 16; o > 0; o >>= 1)
        v += __shfl_down_sync(0xffffffffu, v, o);
    if (lane == 0) tot[warp] = v;
    __syncthreads();

    if (threadIdx.x == 0) {
        float nv       = tot[0];
        float num_pos  = tot[1];
        float pos_term = tot[2];
        float neg_term = tot[3];

        float focal = (num_pos == 0.0f) ? neg_term
                                        : (pos_term + neg_term) / num_pos;
        float inv2nv = 1.0f / (2.0f * nv);
        float invnv  = 1.0f / nv;

        float confidence_loss = 1.0f * focal;             // CONF_W
        float pos_loss   = 1.0f * tot[4] * inv2nv;        // POS_W
        float len_v1     = 0.1f * tot[5] * inv2nv;        // LEN_W
        float len_v2     = 0.1f * tot[6] * inv2nv;
        float trig_v1    = 1.0f * tot[7] * inv2nv;        // TRIG_W
        float trig_v2    = 1.0f * tot[8] * inv2nv;
        float const_loss = 0.5f * tot[9] * invnv;         // CONST_W
        float height     = 0.1f * tot[10] * invnv;        // LEN_W

        float dims = fminf(len_v1 + trig_v1, len_v2 + trig_v2) + height;
        out[0] = confidence_loss + pos_loss + dims + const_loss;
    }
}

extern "C" void kernel_launch(void* const* d_in, const int* in_sizes, int n_in,
                              void* d_out, int out_size) {
    const float* re = (const float*)d_in[0];
    const float* gt = (const float*)d_in[1];
    float* out = (float*)d_out;

    loss_kernel<<<GRID, BLK>>>(re, gt);
    finalize_kernel<<<1, NACC*32>>>(out);
}